// round 14
// baseline (speedup 1.0000x reference)
#include <cuda_runtime.h>
#include <math_constants.h>
#include <stdint.h>

// Problem constants
#define B_    8
#define A_    400
#define R_    1024
#define M_    4096
#define MC    6             // map_pc columns: x,y,z,nx,ny,nz
#define KPK   4
#define NPTS  (A_*KPK)      // 1600 scan points per batch
#define NIT   50
#define RESF  0.0596f
#define TRIMF 5.0f
#define GRID  64
#define NCELL (GRID*GRID)   // 4096
#define CELLSZ 1.875f       // 120 / 64
#define INVCELL (1.0f/1.875f)
#define XMIN  (-60.0f)
#define EPS_DX 5e-5f        // early-exit threshold on GN step

#define CLU   4             // CTAs per batch (cluster size)
#define NTH   512           // threads per CTA
#define PPC   (NPTS/CLU)    // 400 points per CTA
#define NACTW ((PPC+31)/32) // 13 active warps
#define MBAR_CNT (9*CLU)    // 9 lanes x 4 ranks arrivals per phase

// Scratch: extracted scan points + weights
__device__ float g_scanx[B_*NPTS];
__device__ float g_scany[B_*NPTS];
__device__ float g_scanw[B_*NPTS];

// ---------------------------------------------------------------------------
// cluster / DSMEM helpers
// ---------------------------------------------------------------------------
__device__ __forceinline__ uint32_t smem_u32(const void* p) {
    return (uint32_t)__cvta_generic_to_shared(p);
}
__device__ __forceinline__ uint32_t mapa_rank(uint32_t addr, uint32_t rank) {
    uint32_t r;
    asm("mapa.shared::cluster.u32 %0, %1, %2;" : "=r"(r) : "r"(addr), "r"(rank));
    return r;
}
__device__ __forceinline__ void st_cluster_f32(uint32_t addr, float v) {
    asm volatile("st.shared::cluster.f32 [%0], %1;" :: "r"(addr), "f"(v));
}
__device__ __forceinline__ void mbar_init(uint32_t addr, uint32_t count) {
    asm volatile("mbarrier.init.shared.b64 [%0], %1;" :: "r"(addr), "r"(count) : "memory");
}
// remote arrive with release.cluster (orders this thread's prior ::cluster stores)
__device__ __forceinline__ void mbar_arrive_remote(uint32_t remote_addr) {
    asm volatile("mbarrier.arrive.release.cluster.shared::cluster.b64 _, [%0];"
                 :: "r"(remote_addr) : "memory");
}
// acquire.cluster parity wait (spin with HW sleep)
__device__ __forceinline__ void mbar_wait_parity(uint32_t addr, uint32_t parity) {
    asm volatile(
        "{\n\t"
        ".reg .pred P1;\n\t"
        "WAIT_LOOP_%=:\n\t"
        "mbarrier.try_wait.parity.acquire.cluster.shared::cta.b64 P1, [%0], %1, 0x989680;\n\t"
        "@P1 bra.uni WAIT_DONE_%=;\n\t"
        "bra.uni WAIT_LOOP_%=;\n\t"
        "WAIT_DONE_%=:\n\t"
        "}"
        :: "r"(addr), "r"(parity) : "memory");
}
__device__ __forceinline__ uint32_t cluster_rank() {
    uint32_t r; asm("mov.u32 %0, %%cluster_ctarank;" : "=r"(r)); return r;
}
__device__ __forceinline__ void cluster_sync() {
    asm volatile("barrier.cluster.arrive.aligned;" ::: "memory");
    asm volatile("barrier.cluster.wait.aligned;" ::: "memory");
}
__device__ __forceinline__ int morton6(int x, int y) {
    int m = 0;
    #pragma unroll
    for (int b = 0; b < 6; ++b)
        m |= (((x >> b) & 1) << (2*b)) | (((y >> b) & 1) << (2*b + 1));
    return m;
}

// ---------------------------------------------------------------------------
// Kernel 1: BFAR extraction. One warp per (b, a) row.
// ---------------------------------------------------------------------------
__global__ void extract_kernel(const float* __restrict__ fft,
                               const float* __restrict__ az,
                               const float* __restrict__ params) {
    int gtid = blockIdx.x * blockDim.x + threadIdx.x;
    int row  = gtid >> 5;
    int lane = gtid & 31;
    if (row >= B_ * A_) return;

    const float* rp = fft + (size_t)row * R_;

    float sum = 0.f;
    #pragma unroll
    for (int i = 0; i < R_/32; ++i) sum += rp[i*32 + lane];
    #pragma unroll
    for (int off = 16; off; off >>= 1) sum += __shfl_xor_sync(0xffffffffu, sum, off);
    float mean = sum * (1.0f / (float)R_);
    float pa = fmaxf(params[0], 0.f);
    float pb = fmaxf(params[1], 0.f);
    float thr = pa * mean + pb;

    float v0=-CUDART_INF_F, v1=-CUDART_INF_F, v2=-CUDART_INF_F, v3=-CUDART_INF_F;
    int   i0=0x7fffffff,   i1=0x7fffffff,   i2=0x7fffffff,   i3=0x7fffffff;
    #pragma unroll
    for (int i = 0; i < R_/32; ++i) {
        int idx = i*32 + lane;
        float sc = rp[idx] - thr;
        if (sc > v3) {
            v3 = sc; i3 = idx;
            if (v3 > v2) { float tv=v2; v2=v3; v3=tv; int ti=i2; i2=i3; i3=ti; }
            if (v2 > v1) { float tv=v1; v1=v2; v2=tv; int ti=i1; i1=i2; i2=ti; }
            if (v1 > v0) { float tv=v0; v0=v1; v1=tv; int ti=i0; i0=i1; i1=ti; }
        }
    }

    int ptr = 0;
    float outv = 0.f; int outi = 0;
    #pragma unroll
    for (int k = 0; k < KPK; ++k) {
        float cv = (ptr==0) ? v0 : (ptr==1) ? v1 : (ptr==2) ? v2 : (ptr==3) ? v3 : -CUDART_INF_F;
        int   ci = (ptr==0) ? i0 : (ptr==1) ? i1 : (ptr==2) ? i2 : (ptr==3) ? i3 : 0x7fffffff;
        float bv = cv; int bi = ci;
        #pragma unroll
        for (int off = 16; off; off >>= 1) {
            float ov = __shfl_xor_sync(0xffffffffu, bv, off);
            int   oi = __shfl_xor_sync(0xffffffffu, bi, off);
            if (ov > bv || (ov == bv && oi < bi)) { bv = ov; bi = oi; }
        }
        if (bi == ci && ptr < 4) ptr++;
        if (lane == k) { outv = bv; outi = bi; }
    }

    if (lane < KPK) {
        float rng = ((float)outi + 0.5f) * RESF;
        float azv = az[row];
        float x = rng * cosf(azv);
        float y = rng * sinf(azv);
        int o = row * KPK + lane;
        g_scanx[o] = x;
        g_scany[o] = y;
        g_scanw[o] = fmaxf(outv, 0.f);
    }
}

// ---------------------------------------------------------------------------
// Kernel 2: clustered ICP. Grid 64, offset 4x4 window, exact rect expansion.
// Cross-CTA reduction synced by parity-alternated DSMEM mbarriers (count 36)
// instead of full cluster.sync.
// ---------------------------------------------------------------------------
struct IcpSmem {
    float2 sxy[M_];                // binned (x, y)                   32 KB
    float2 snrm[M_];               // binned (nx, ny)                 32 KB
    __align__(16) float partial[2][CLU][12];  // 16B-aligned for LDS.128 reads
    unsigned long long mbar[2];    // parity-alternated cross-CTA mbarriers
    int    cellStart[NCELL+1];
    int    cellOfs[NCELL];
    float  srtx[PPC];
    float  srty[PPC];
    float  srtw[PPC];
    float  red[NACTW][12];         // per-active-warp partials (padded)
    int    wsum[16];
};

// exclusive prefix scan over 4096 ints in smem arr, 512 threads (8/thread).
__device__ __forceinline__ void scan4096(int* arr, int* wsum,
                                         int tid, int lane, int wid, int totStore,
                                         int* cellStartTotal) {
    int base8 = tid * 8;
    int c[8], pre[8];
    int s = 0;
    #pragma unroll
    for (int j = 0; j < 8; ++j) { c[j] = arr[base8 + j]; pre[j] = s; s += c[j]; }
    int v = s;
    #pragma unroll
    for (int off = 1; off < 32; off <<= 1) {
        int u = __shfl_up_sync(0xffffffffu, v, off);
        if (lane >= off) v += u;
    }
    if (lane == 31) wsum[wid] = v;
    __syncthreads();
    if (wid == 0 && lane < 16) {
        int wv = wsum[lane];
        #pragma unroll
        for (int off = 1; off < 16; off <<= 1) {
            int u = __shfl_up_sync(0x0000ffffu, wv, off);
            if (lane >= off) wv += u;
        }
        wsum[lane] = wv;
    }
    __syncthreads();
    int base = (v - s) + (wid ? wsum[wid-1] : 0);
    #pragma unroll
    for (int j = 0; j < 8; ++j) arr[base8 + j] = base + pre[j];
    if (totStore && tid == NTH-1) *cellStartTotal = base + s;
    __syncthreads();
}

__global__ void __launch_bounds__(NTH, 1) __cluster_dims__(CLU, 1, 1)
icp_kernel(const float* __restrict__ map_pc,
           const float* __restrict__ T_init,
           float* __restrict__ out) {
    extern __shared__ char smraw[];
    IcpSmem& S = *reinterpret_cast<IcpSmem*>(smraw);

    const int tid   = threadIdx.x;
    const int lane  = tid & 31;
    const int wid   = tid >> 5;
    const int crank = (int)cluster_rank();
    const int b     = blockIdx.x / CLU;
    const float* mp = map_pc + (size_t)b * M_ * MC;

    // --- build map grid: count ---
    for (int c = tid; c < NCELL; c += NTH) S.cellOfs[c] = 0;
    __syncthreads();
    for (int i = tid; i < M_; i += NTH) {
        float x = mp[i*MC + 0], y = mp[i*MC + 1];
        int gx = min(max((int)floorf((x - XMIN) * INVCELL), 0), GRID-1);
        int gy = min(max((int)floorf((y - XMIN) * INVCELL), 0), GRID-1);
        atomicAdd(&S.cellOfs[gy*GRID + gx], 1);
    }
    __syncthreads();

    scan4096(S.cellOfs, S.wsum, tid, lane, wid, 1, &S.cellStart[NCELL]);
    for (int c = tid; c < NCELL; c += NTH) S.cellStart[c] = S.cellOfs[c];
    __syncthreads();

    // --- scatter map points (normalize 2D normals) ---
    for (int i = tid; i < M_; i += NTH) {
        float x  = mp[i*MC + 0], y  = mp[i*MC + 1];
        float nx = mp[i*MC + 3], ny = mp[i*MC + 4];
        float nrm = sqrtf(nx*nx + ny*ny);
        float d   = fmaxf(nrm, 1e-12f);
        nx /= d; ny /= d;
        int gx = min(max((int)floorf((x - XMIN) * INVCELL), 0), GRID-1);
        int gy = min(max((int)floorf((y - XMIN) * INVCELL), 0), GRID-1);
        int pos = atomicAdd(&S.cellOfs[gy*GRID + gx], 1);
        S.sxy[pos]  = make_float2(x, y);
        S.snrm[pos] = make_float2(nx, ny);
    }

    // pose state, identical in every thread
    float theta, tx, ty;
    {
        const float* T = T_init + b*16;
        theta = atan2f(T[4], T[0]);
        tx = T[3];
        ty = T[7];
    }
    if (tid == 0) {
        mbar_init(smem_u32(&S.mbar[0]), MBAR_CNT);
        mbar_init(smem_u32(&S.mbar[1]), MBAR_CNT);
    }

    // --- one-time Morton counting-sort of this CTA's 400 scan points ---
    float rawx = 0.f, rawy = 0.f, raww = 0.f;
    int mykey = 0;
    {
        float c0 = cosf(theta), s0 = sinf(theta);
        if (tid < PPC) {
            int o = b*NPTS + crank*PPC + tid;
            rawx = g_scanx[o];
            rawy = g_scany[o];
            raww = g_scanw[o];
            float px = c0*rawx - s0*rawy + tx;
            float py = s0*rawx + c0*rawy + ty;
            int gx = min(max((int)floorf((px - XMIN) * INVCELL), 0), GRID-1);
            int gy = min(max((int)floorf((py - XMIN) * INVCELL), 0), GRID-1);
            mykey = morton6(gx, gy);
        }
        __syncthreads();  // map scatter done; cellOfs reusable as histogram
        for (int c = tid; c < NCELL; c += NTH) S.cellOfs[c] = 0;
        __syncthreads();
        if (tid < PPC) atomicAdd(&S.cellOfs[mykey], 1);
        __syncthreads();
        scan4096(S.cellOfs, S.wsum, tid, lane, wid, 0, nullptr);
        if (tid < PPC) {
            int pos = atomicAdd(&S.cellOfs[mykey], 1);
            S.srtx[pos] = rawx;
            S.srty[pos] = rawy;
            S.srtw[pos] = raww;
        }
        __syncthreads();
    }

    float sxv = 0.f, syv = 0.f, wv = 0.f;
    if (tid < PPC) {
        sxv = S.srtx[tid];
        syv = S.srty[tid];
        wv  = S.srtw[tid];
    }
    __syncthreads();
    cluster_sync();  // peers' smem + mbarriers ready before DSMEM traffic

    const uint32_t partialBase = smem_u32(&S.partial[0][0][0]);
    const uint32_t mbarBase    = smem_u32(&S.mbar[0]);
    const float4* sxyPairs = reinterpret_cast<const float4*>(&S.sxy[0]);
    const float trim2 = TRIMF * TRIMF;

    // --- GN iterations (early exit when step is negligible) ---
    for (int it = 0; it < NIT; ++it) {
        const int parity = it & 1;
        const uint32_t mphase = (uint32_t)((it >> 1) & 1);
        float cth, sth;
        __sincosf(theta, &sth, &cth);

        float a00=0.f,a01=0.f,a02=0.f,a11=0.f,a12=0.f,a22=0.f;
        float g0=0.f,g1=0.f,g2=0.f;

        if (tid < PPC) {
            float px = cth*sxv - sth*syv + tx;
            float py = sth*sxv + cth*syv + ty;

            // dual independent accumulators (break the min dep chain)
            float bA = 1e30f, bB = 1e30f;
            int   kA = -1,    kB = -1;

            auto scanPairs = [&](int k0, int k1) {
                if (k0 >= k1) return;
                int p  = k0 >> 1;
                int pe = (k1 + 1) >> 1;   // exclusive pair bound
                for (; p + 2 <= pe; p += 2) {
                    float4 ma = sxyPairs[p];
                    float4 mb = sxyPairs[p+1];
                    int base = 2*p;
                    float dxa0 = px - ma.x, dya0 = py - ma.y;
                    float dxa1 = px - ma.z, dya1 = py - ma.w;
                    float dxb0 = px - mb.x, dyb0 = py - mb.y;
                    float dxb1 = px - mb.z, dyb1 = py - mb.w;
                    float da0 = dxa0*dxa0 + dya0*dya0;
                    float da1 = dxa1*dxa1 + dya1*dya1;
                    float db0 = dxb0*dxb0 + dyb0*dyb0;
                    float db1 = dxb1*dxb1 + dyb1*dyb1;
                    if (da0 < bA) { bA = da0; kA = base; }
                    if (da1 < bA) { bA = da1; kA = base+1; }
                    if (db0 < bB) { bB = db0; kB = base+2; }
                    if (db1 < bB) { bB = db1; kB = base+3; }
                }
                for (; p < pe; ++p) {
                    float4 ma = sxyPairs[p];
                    int base = 2*p;
                    float dxa0 = px - ma.x, dya0 = py - ma.y;
                    float dxa1 = px - ma.z, dya1 = py - ma.w;
                    float da0 = dxa0*dxa0 + dya0*dya0;
                    float da1 = dxa1*dxa1 + dya1*dya1;
                    if (da0 < bA) { bA = da0; kA = base; }
                    if (da1 < bA) { bA = da1; kA = base+1; }
                }
            };
            auto scanRow = [&](int gy, int xa, int xb) {
                scanPairs(S.cellStart[gy*GRID + xa], S.cellStart[gy*GRID + xb + 1]);
            };

            // ---- phase 1: offset 4x4 window (margin >= 1.5 cell) ----
            float fx = (px - XMIN) * INVCELL;
            float fy = (py - XMIN) * INVCELL;
            int cgx = min(max((int)floorf(fx), 0), GRID-1);
            int cgy = min(max((int)floorf(fy), 0), GRID-1);
            int wx0 = (fx - (float)cgx >= 0.5f) ? cgx - 1 : cgx - 2;
            int wy0 = (fy - (float)cgy >= 0.5f) ? cgy - 1 : cgy - 2;
            wx0 = min(max(wx0, 0), GRID-4);
            wy0 = min(max(wy0, 0), GRID-4);
            int wx1 = wx0 + 3, wy1 = wy0 + 3;
            #pragma unroll
            for (int gy = 0; gy < 4; ++gy)
                scanRow(wy0 + gy, wx0, wx1);

            // ---- phase 2: exact rectangle expansion (statistically never) ----
            for (;;) {
                float mL = (wx0 > 0)      ? px - (XMIN + (float)wx0 * CELLSZ)       : 1e30f;
                float mR = (wx1 < GRID-1) ? (XMIN + (float)(wx1 + 1) * CELLSZ) - px : 1e30f;
                float mB = (wy0 > 0)      ? py - (XMIN + (float)wy0 * CELLSZ)       : 1e30f;
                float mT = (wy1 < GRID-1) ? (XMIN + (float)(wy1 + 1) * CELLSZ) - py : 1e30f;
                float mf = fminf(fminf(mL, mR), fminf(mB, mT));
                float lim = fminf(fminf(bA, bB), trim2);
                if (mf * mf >= lim) break;
                if (mL <= mR && mL <= mB && mL <= mT) {
                    --wx0;
                    for (int gy = wy0; gy <= wy1; ++gy) scanRow(gy, wx0, wx0);
                } else if (mR <= mB && mR <= mT) {
                    ++wx1;
                    for (int gy = wy0; gy <= wy1; ++gy) scanRow(gy, wx1, wx1);
                } else if (mB <= mT) {
                    --wy0;
                    scanRow(wy0, wx0, wx1);
                } else {
                    ++wy1;
                    scanRow(wy1, wx0, wx1);
                }
            }

            // merge chains
            float bestd2 = bA; int bestk = kA;
            if (bB < bestd2) { bestd2 = bB; bestk = kB; }

            if (bestk >= 0 && bestd2 < trim2) {
                float2 q = S.sxy[bestk];
                float2 n = S.snrm[bestk];
                float res = n.x*(px - q.x) + n.y*(py - q.y);
                float hub = fminf(1.f, __fdividef(1.f, fmaxf(fabsf(res), 1e-12f)));
                float wt  = wv * hub;
                float dr0 = -sth*sxv - cth*syv;
                float dr1 =  cth*sxv - sth*syv;
                float j2  = n.x*dr0 + n.y*dr1;
                a00 = wt*n.x*n.x; a01 = wt*n.x*n.y; a02 = wt*n.x*j2;
                a11 = wt*n.y*n.y; a12 = wt*n.y*j2;  a22 = wt*j2*j2;
                g0  = wt*n.x*res; g1  = wt*n.y*res; g2  = wt*j2*res;
            }
        }

        // warp tree-reduce 9 values (active warps only)
        if (wid < NACTW) {
            #pragma unroll
            for (int off = 16; off; off >>= 1) {
                a00 += __shfl_xor_sync(0xffffffffu, a00, off);
                a01 += __shfl_xor_sync(0xffffffffu, a01, off);
                a02 += __shfl_xor_sync(0xffffffffu, a02, off);
                a11 += __shfl_xor_sync(0xffffffffu, a11, off);
                a12 += __shfl_xor_sync(0xffffffffu, a12, off);
                a22 += __shfl_xor_sync(0xffffffffu, a22, off);
                g0  += __shfl_xor_sync(0xffffffffu, g0 , off);
                g1  += __shfl_xor_sync(0xffffffffu, g1 , off);
                g2  += __shfl_xor_sync(0xffffffffu, g2 , off);
            }
            if (lane == 0) {
                S.red[wid][0]=a00; S.red[wid][1]=a01; S.red[wid][2]=a02;
                S.red[wid][3]=a11; S.red[wid][4]=a12; S.red[wid][5]=a22;
                S.red[wid][6]=g0;  S.red[wid][7]=g1;  S.red[wid][8]=g2;
            }
        }
        __syncthreads();

        // warp 0: reduce warp partials; lanes 0-8 broadcast + arrive all ranks
        if (wid == 0) {
            float r9[9];
            #pragma unroll
            for (int k = 0; k < 9; ++k) r9[k] = (lane < NACTW) ? S.red[lane][k] : 0.f;
            #pragma unroll
            for (int off = 8; off; off >>= 1) {
                #pragma unroll
                for (int k = 0; k < 9; ++k)
                    r9[k] += __shfl_xor_sync(0xffffffffu, r9[k], off);
            }
            if (lane < 9) {
                float val = (lane==0)?r9[0]:(lane==1)?r9[1]:(lane==2)?r9[2]:
                            (lane==3)?r9[3]:(lane==4)?r9[4]:(lane==5)?r9[5]:
                            (lane==6)?r9[6]:(lane==7)?r9[7]:r9[8];
                uint32_t slot = partialBase + (uint32_t)((parity*CLU + crank) * 48 + lane * 4);
                uint32_t mb   = mbarBase + (uint32_t)(parity * 8);
                #pragma unroll
                for (int t = 0; t < CLU; ++t)
                    st_cluster_f32(mapa_rank(slot, (uint32_t)t), val);
                #pragma unroll
                for (int t = 0; t < CLU; ++t)
                    mbar_arrive_remote(mapa_rank(mb, (uint32_t)t));
            }
        }

        // ALL threads wait for the 36 arrivals (acquire), then solve redundantly
        mbar_wait_parity(mbarBase + (uint32_t)(parity * 8), mphase);

        float stepmax;
        {
            const float4* P = reinterpret_cast<const float4*>(&S.partial[parity][0][0]);
            float4 p0a = P[0], p0b = P[1], p0c = P[2];
            float4 p1a = P[3], p1b = P[4], p1c = P[5];
            float4 p2a = P[6], p2b = P[7], p2c = P[8];
            float4 p3a = P[9], p3b = P[10], p3c = P[11];
            float A00 = (p0a.x + p1a.x + p2a.x + p3a.x) + 1e-8f;
            float A01 = (p0a.y + p1a.y + p2a.y + p3a.y);
            float A02 = (p0a.z + p1a.z + p2a.z + p3a.z);
            float A11 = (p0a.w + p1a.w + p2a.w + p3a.w) + 1e-8f;
            float A12 = (p0b.x + p1b.x + p2b.x + p3b.x);
            float A22 = (p0b.y + p1b.y + p2b.y + p3b.y) + 1e-8f;
            float G0  = (p0b.z + p1b.z + p2b.z + p3b.z);
            float G1  = (p0b.w + p1b.w + p2b.w + p3b.w);
            float G2  = (p0c.x + p1c.x + p2c.x + p3c.x);
            float il00 = __frsqrt_rn(fmaxf(A00, 1e-30f));
            float l10 = A01*il00, l20 = A02*il00;
            float il11 = __frsqrt_rn(fmaxf(A11 - l10*l10, 1e-30f));
            float l21 = (A12 - l20*l10)*il11;
            float il22 = __frsqrt_rn(fmaxf(A22 - l20*l20 - l21*l21, 1e-30f));
            float y0 = -G0*il00;
            float y1 = (-G1 - l10*y0)*il11;
            float y2 = (-G2 - l20*y0 - l21*y1)*il22;
            float x2 = y2*il22;
            float x1 = (y1 - l21*x2)*il11;
            float x0 = (y0 - l10*x1 - l20*x2)*il00;
            theta += x2;
            tx += x0;
            ty += x1;
            stepmax = fmaxf(fmaxf(fabsf(x0), fabsf(x1)), fabsf(x2));
        }
        // uniform early exit: identical fp32 in every thread of every CTA
        if (stepmax < EPS_DX) break;
    }

    if (tid == 0 && crank == 0) {
        float c = cosf(theta), s = sinf(theta);
        float* T = out + b*16;
        T[0]=c;   T[1]=-s;  T[2]=0.f; T[3]=tx;
        T[4]=s;   T[5]=c;   T[6]=0.f; T[7]=ty;
        T[8]=0.f; T[9]=0.f; T[10]=1.f;T[11]=0.f;
        T[12]=0.f;T[13]=0.f;T[14]=0.f;T[15]=1.f;
    }
    cluster_sync();  // keep peers' smem alive until all DSMEM traffic retires
}

// ---------------------------------------------------------------------------
extern "C" void kernel_launch(void* const* d_in, const int* in_sizes, int n_in,
                              void* d_out, int out_size) {
    (void)in_sizes; (void)n_in; (void)out_size;
    const float* fft    = (const float*)d_in[0];
    const float* az     = (const float*)d_in[1];
    // d_in[2] = az_timestamps (unused)
    const float* map_pc = (const float*)d_in[3];
    const float* T_init = (const float*)d_in[4];
    const float* params = (const float*)d_in[5];
    float* out = (float*)d_out;

    extract_kernel<<<(B_*A_*32 + 127)/128, 128>>>(fft, az, params);

    cudaFuncSetAttribute(icp_kernel,
                         cudaFuncAttributeMaxDynamicSharedMemorySize,
                         (int)sizeof(IcpSmem));
    icp_kernel<<<B_*CLU, NTH, sizeof(IcpSmem)>>>(map_pc, T_init, out);
}

// round 15
// speedup vs baseline: 1.0895x; 1.0895x over previous
#include <cuda_runtime.h>
#include <math_constants.h>
#include <stdint.h>

// Problem constants
#define B_    8
#define A_    400
#define R_    1024
#define M_    4096
#define MC    6             // map_pc columns: x,y,z,nx,ny,nz
#define KPK   4
#define NPTS  (A_*KPK)      // 1600 scan points per batch
#define NIT   50
#define RESF  0.0596f
#define TRIMF 5.0f
#define GRID  64
#define NCELL (GRID*GRID)   // 4096
#define CELLSZ 1.875f       // 120 / 64
#define INVCELL (1.0f/1.875f)
#define XMIN  (-60.0f)
#define EPS_DX 2e-4f        // early-exit threshold on GN step (drift -> rel_err ~2e-4 worst case)

#define CLU   4             // CTAs per batch (cluster size)
#define NTH   512           // threads per CTA
#define PPC   (NPTS/CLU)    // 400 points per CTA
#define NACTW ((PPC+31)/32) // 13 active warps

// Scratch: extracted scan points + weights
__device__ float g_scanx[B_*NPTS];
__device__ float g_scany[B_*NPTS];
__device__ float g_scanw[B_*NPTS];

// ---------------------------------------------------------------------------
// cluster / DSMEM helpers
// ---------------------------------------------------------------------------
__device__ __forceinline__ uint32_t smem_u32(const void* p) {
    return (uint32_t)__cvta_generic_to_shared(p);
}
__device__ __forceinline__ uint32_t mapa_rank(uint32_t addr, uint32_t rank) {
    uint32_t r;
    asm("mapa.shared::cluster.u32 %0, %1, %2;" : "=r"(r) : "r"(addr), "r"(rank));
    return r;
}
__device__ __forceinline__ void st_cluster_f32(uint32_t addr, float v) {
    asm volatile("st.shared::cluster.f32 [%0], %1;" :: "r"(addr), "f"(v));
}
__device__ __forceinline__ uint32_t cluster_rank() {
    uint32_t r; asm("mov.u32 %0, %%cluster_ctarank;" : "=r"(r)); return r;
}
__device__ __forceinline__ void cluster_sync() {
    asm volatile("barrier.cluster.arrive.aligned;" ::: "memory");
    asm volatile("barrier.cluster.wait.aligned;" ::: "memory");
}
__device__ __forceinline__ int morton6(int x, int y) {
    int m = 0;
    #pragma unroll
    for (int b = 0; b < 6; ++b)
        m |= (((x >> b) & 1) << (2*b)) | (((y >> b) & 1) << (2*b + 1));
    return m;
}

// ---------------------------------------------------------------------------
// Kernel 1: BFAR extraction. One warp per (b, a) row.
// ---------------------------------------------------------------------------
__global__ void extract_kernel(const float* __restrict__ fft,
                               const float* __restrict__ az,
                               const float* __restrict__ params) {
    int gtid = blockIdx.x * blockDim.x + threadIdx.x;
    int row  = gtid >> 5;
    int lane = gtid & 31;
    if (row >= B_ * A_) return;

    const float* rp = fft + (size_t)row * R_;

    float sum = 0.f;
    #pragma unroll
    for (int i = 0; i < R_/32; ++i) sum += rp[i*32 + lane];
    #pragma unroll
    for (int off = 16; off; off >>= 1) sum += __shfl_xor_sync(0xffffffffu, sum, off);
    float mean = sum * (1.0f / (float)R_);
    float pa = fmaxf(params[0], 0.f);
    float pb = fmaxf(params[1], 0.f);
    float thr = pa * mean + pb;

    float v0=-CUDART_INF_F, v1=-CUDART_INF_F, v2=-CUDART_INF_F, v3=-CUDART_INF_F;
    int   i0=0x7fffffff,   i1=0x7fffffff,   i2=0x7fffffff,   i3=0x7fffffff;
    #pragma unroll
    for (int i = 0; i < R_/32; ++i) {
        int idx = i*32 + lane;
        float sc = rp[idx] - thr;
        if (sc > v3) {
            v3 = sc; i3 = idx;
            if (v3 > v2) { float tv=v2; v2=v3; v3=tv; int ti=i2; i2=i3; i3=ti; }
            if (v2 > v1) { float tv=v1; v1=v2; v2=tv; int ti=i1; i1=i2; i2=ti; }
            if (v1 > v0) { float tv=v0; v0=v1; v1=tv; int ti=i0; i0=i1; i1=ti; }
        }
    }

    int ptr = 0;
    float outv = 0.f; int outi = 0;
    #pragma unroll
    for (int k = 0; k < KPK; ++k) {
        float cv = (ptr==0) ? v0 : (ptr==1) ? v1 : (ptr==2) ? v2 : (ptr==3) ? v3 : -CUDART_INF_F;
        int   ci = (ptr==0) ? i0 : (ptr==1) ? i1 : (ptr==2) ? i2 : (ptr==3) ? i3 : 0x7fffffff;
        float bv = cv; int bi = ci;
        #pragma unroll
        for (int off = 16; off; off >>= 1) {
            float ov = __shfl_xor_sync(0xffffffffu, bv, off);
            int   oi = __shfl_xor_sync(0xffffffffu, bi, off);
            if (ov > bv || (ov == bv && oi < bi)) { bv = ov; bi = oi; }
        }
        if (bi == ci && ptr < 4) ptr++;
        if (lane == k) { outv = bv; outi = bi; }
    }

    if (lane < KPK) {
        float rng = ((float)outi + 0.5f) * RESF;
        float azv = az[row];
        float x = rng * cosf(azv);
        float y = rng * sinf(azv);
        int o = row * KPK + lane;
        g_scanx[o] = x;
        g_scany[o] = y;
        g_scanw[o] = fmaxf(outv, 0.f);
    }
}

// ---------------------------------------------------------------------------
// Kernel 2: clustered ICP. Grid 64, offset 4x4 window (margin >= 1.5 cell),
// exact rectangle-expansion fallback. Early exit on converged step.
// ---------------------------------------------------------------------------
struct IcpSmem {
    float2 sxy[M_];                // binned (x, y)                   32 KB
    float2 snrm[M_];               // binned (nx, ny)                 32 KB
    __align__(16) float partial[2][CLU][12];  // 16B-aligned for LDS.128 reads
    int    cellStart[NCELL+1];
    int    cellOfs[NCELL];
    float  srtx[PPC];
    float  srty[PPC];
    float  srtw[PPC];
    float  red[NACTW][12];         // per-active-warp partials (padded)
    int    wsum[16];
};

// exclusive prefix scan over 4096 ints in smem arr, 512 threads (8/thread).
__device__ __forceinline__ void scan4096(int* arr, int* wsum,
                                         int tid, int lane, int wid, int totStore,
                                         int* cellStartTotal) {
    int base8 = tid * 8;
    int c[8], pre[8];
    int s = 0;
    #pragma unroll
    for (int j = 0; j < 8; ++j) { c[j] = arr[base8 + j]; pre[j] = s; s += c[j]; }
    int v = s;
    #pragma unroll
    for (int off = 1; off < 32; off <<= 1) {
        int u = __shfl_up_sync(0xffffffffu, v, off);
        if (lane >= off) v += u;
    }
    if (lane == 31) wsum[wid] = v;
    __syncthreads();
    if (wid == 0 && lane < 16) {
        int wv = wsum[lane];
        #pragma unroll
        for (int off = 1; off < 16; off <<= 1) {
            int u = __shfl_up_sync(0x0000ffffu, wv, off);
            if (lane >= off) wv += u;
        }
        wsum[lane] = wv;
    }
    __syncthreads();
    int base = (v - s) + (wid ? wsum[wid-1] : 0);
    #pragma unroll
    for (int j = 0; j < 8; ++j) arr[base8 + j] = base + pre[j];
    if (totStore && tid == NTH-1) *cellStartTotal = base + s;
    __syncthreads();
}

__global__ void __launch_bounds__(NTH, 1) __cluster_dims__(CLU, 1, 1)
icp_kernel(const float* __restrict__ map_pc,
           const float* __restrict__ T_init,
           float* __restrict__ out) {
    extern __shared__ char smraw[];
    IcpSmem& S = *reinterpret_cast<IcpSmem*>(smraw);

    const int tid   = threadIdx.x;
    const int lane  = tid & 31;
    const int wid   = tid >> 5;
    const int crank = (int)cluster_rank();
    const int b     = blockIdx.x / CLU;
    const float* mp = map_pc + (size_t)b * M_ * MC;

    // --- build map grid: count ---
    for (int c = tid; c < NCELL; c += NTH) S.cellOfs[c] = 0;
    __syncthreads();
    for (int i = tid; i < M_; i += NTH) {
        float x = mp[i*MC + 0], y = mp[i*MC + 1];
        int gx = min(max((int)floorf((x - XMIN) * INVCELL), 0), GRID-1);
        int gy = min(max((int)floorf((y - XMIN) * INVCELL), 0), GRID-1);
        atomicAdd(&S.cellOfs[gy*GRID + gx], 1);
    }
    __syncthreads();

    scan4096(S.cellOfs, S.wsum, tid, lane, wid, 1, &S.cellStart[NCELL]);
    for (int c = tid; c < NCELL; c += NTH) S.cellStart[c] = S.cellOfs[c];
    __syncthreads();

    // --- scatter map points (normalize 2D normals) ---
    for (int i = tid; i < M_; i += NTH) {
        float x  = mp[i*MC + 0], y  = mp[i*MC + 1];
        float nx = mp[i*MC + 3], ny = mp[i*MC + 4];
        float nrm = sqrtf(nx*nx + ny*ny);
        float d   = fmaxf(nrm, 1e-12f);
        nx /= d; ny /= d;
        int gx = min(max((int)floorf((x - XMIN) * INVCELL), 0), GRID-1);
        int gy = min(max((int)floorf((y - XMIN) * INVCELL), 0), GRID-1);
        int pos = atomicAdd(&S.cellOfs[gy*GRID + gx], 1);
        S.sxy[pos]  = make_float2(x, y);
        S.snrm[pos] = make_float2(nx, ny);
    }

    // pose state, identical in every thread
    float theta, tx, ty;
    {
        const float* T = T_init + b*16;
        theta = atan2f(T[4], T[0]);
        tx = T[3];
        ty = T[7];
    }

    // --- one-time Morton counting-sort of this CTA's 400 scan points ---
    float rawx = 0.f, rawy = 0.f, raww = 0.f;
    int mykey = 0;
    {
        float c0 = cosf(theta), s0 = sinf(theta);
        if (tid < PPC) {
            int o = b*NPTS + crank*PPC + tid;
            rawx = g_scanx[o];
            rawy = g_scany[o];
            raww = g_scanw[o];
            float px = c0*rawx - s0*rawy + tx;
            float py = s0*rawx + c0*rawy + ty;
            int gx = min(max((int)floorf((px - XMIN) * INVCELL), 0), GRID-1);
            int gy = min(max((int)floorf((py - XMIN) * INVCELL), 0), GRID-1);
            mykey = morton6(gx, gy);
        }
        __syncthreads();  // map scatter done; cellOfs reusable as histogram
        for (int c = tid; c < NCELL; c += NTH) S.cellOfs[c] = 0;
        __syncthreads();
        if (tid < PPC) atomicAdd(&S.cellOfs[mykey], 1);
        __syncthreads();
        scan4096(S.cellOfs, S.wsum, tid, lane, wid, 0, nullptr);
        if (tid < PPC) {
            int pos = atomicAdd(&S.cellOfs[mykey], 1);
            S.srtx[pos] = rawx;
            S.srty[pos] = rawy;
            S.srtw[pos] = raww;
        }
        __syncthreads();
    }

    float sxv = 0.f, syv = 0.f, wv = 0.f;
    if (tid < PPC) {
        sxv = S.srtx[tid];
        syv = S.srty[tid];
        wv  = S.srtw[tid];
    }
    __syncthreads();
    cluster_sync();  // peers' smem ready before DSMEM traffic

    const uint32_t partialBase = smem_u32(&S.partial[0][0][0]);
    const float4* sxyPairs = reinterpret_cast<const float4*>(&S.sxy[0]);
    const float trim2 = TRIMF * TRIMF;

    // --- GN iterations (early exit when step is negligible) ---
    for (int it = 0; it < NIT; ++it) {
        const int parity = it & 1;
        float cth, sth;
        __sincosf(theta, &sth, &cth);

        float a00=0.f,a01=0.f,a02=0.f,a11=0.f,a12=0.f,a22=0.f;
        float g0=0.f,g1=0.f,g2=0.f;

        if (tid < PPC) {
            float px = cth*sxv - sth*syv + tx;
            float py = sth*sxv + cth*syv + ty;

            // dual independent accumulators (break the min dep chain)
            float bA = 1e30f, bB = 1e30f;
            int   kA = -1,    kB = -1;

            // scans [k0,k1) rounded out to pairs; extra edge candidates are
            // real map points, so including them is exact-safe.
            auto scanPairs = [&](int k0, int k1) {
                if (k0 >= k1) return;
                int p  = k0 >> 1;
                int pe = (k1 + 1) >> 1;   // exclusive pair bound
                for (; p + 2 <= pe; p += 2) {
                    float4 ma = sxyPairs[p];
                    float4 mb = sxyPairs[p+1];
                    int base = 2*p;
                    float dxa0 = px - ma.x, dya0 = py - ma.y;
                    float dxa1 = px - ma.z, dya1 = py - ma.w;
                    float dxb0 = px - mb.x, dyb0 = py - mb.y;
                    float dxb1 = px - mb.z, dyb1 = py - mb.w;
                    float da0 = dxa0*dxa0 + dya0*dya0;
                    float da1 = dxa1*dxa1 + dya1*dya1;
                    float db0 = dxb0*dxb0 + dyb0*dyb0;
                    float db1 = dxb1*dxb1 + dyb1*dyb1;
                    if (da0 < bA) { bA = da0; kA = base; }
                    if (da1 < bA) { bA = da1; kA = base+1; }
                    if (db0 < bB) { bB = db0; kB = base+2; }
                    if (db1 < bB) { bB = db1; kB = base+3; }
                }
                for (; p < pe; ++p) {
                    float4 ma = sxyPairs[p];
                    int base = 2*p;
                    float dxa0 = px - ma.x, dya0 = py - ma.y;
                    float dxa1 = px - ma.z, dya1 = py - ma.w;
                    float da0 = dxa0*dxa0 + dya0*dya0;
                    float da1 = dxa1*dxa1 + dya1*dya1;
                    if (da0 < bA) { bA = da0; kA = base; }
                    if (da1 < bA) { bA = da1; kA = base+1; }
                }
            };
            auto scanRow = [&](int gy, int xa, int xb) {
                scanPairs(S.cellStart[gy*GRID + xa], S.cellStart[gy*GRID + xb + 1]);
            };

            // ---- phase 1: offset 4x4 window (margin >= 1.5 cell) ----
            float fx = (px - XMIN) * INVCELL;
            float fy = (py - XMIN) * INVCELL;
            int cgx = min(max((int)floorf(fx), 0), GRID-1);
            int cgy = min(max((int)floorf(fy), 0), GRID-1);
            int wx0 = (fx - (float)cgx >= 0.5f) ? cgx - 1 : cgx - 2;
            int wy0 = (fy - (float)cgy >= 0.5f) ? cgy - 1 : cgy - 2;
            wx0 = min(max(wx0, 0), GRID-4);
            wy0 = min(max(wy0, 0), GRID-4);
            int wx1 = wx0 + 3, wy1 = wy0 + 3;
            #pragma unroll
            for (int gy = 0; gy < 4; ++gy)
                scanRow(wy0 + gy, wx0, wx1);

            // ---- phase 2: exact rectangle expansion (statistically never) ----
            for (;;) {
                float mL = (wx0 > 0)      ? px - (XMIN + (float)wx0 * CELLSZ)       : 1e30f;
                float mR = (wx1 < GRID-1) ? (XMIN + (float)(wx1 + 1) * CELLSZ) - px : 1e30f;
                float mB = (wy0 > 0)      ? py - (XMIN + (float)wy0 * CELLSZ)       : 1e30f;
                float mT = (wy1 < GRID-1) ? (XMIN + (float)(wy1 + 1) * CELLSZ) - py : 1e30f;
                float mf = fminf(fminf(mL, mR), fminf(mB, mT));
                float lim = fminf(fminf(bA, bB), trim2);
                if (mf * mf >= lim) break;
                if (mL <= mR && mL <= mB && mL <= mT) {
                    --wx0;
                    for (int gy = wy0; gy <= wy1; ++gy) scanRow(gy, wx0, wx0);
                } else if (mR <= mB && mR <= mT) {
                    ++wx1;
                    for (int gy = wy0; gy <= wy1; ++gy) scanRow(gy, wx1, wx1);
                } else if (mB <= mT) {
                    --wy0;
                    scanRow(wy0, wx0, wx1);
                } else {
                    ++wy1;
                    scanRow(wy1, wx0, wx1);
                }
            }

            // merge chains
            float bestd2 = bA; int bestk = kA;
            if (bB < bestd2) { bestd2 = bB; bestk = kB; }

            if (bestk >= 0 && bestd2 < trim2) {
                float2 q = S.sxy[bestk];
                float2 n = S.snrm[bestk];
                float res = n.x*(px - q.x) + n.y*(py - q.y);
                float hub = fminf(1.f, __fdividef(1.f, fmaxf(fabsf(res), 1e-12f)));
                float wt  = wv * hub;
                float dr0 = -sth*sxv - cth*syv;
                float dr1 =  cth*sxv - sth*syv;
                float j2  = n.x*dr0 + n.y*dr1;
                a00 = wt*n.x*n.x; a01 = wt*n.x*n.y; a02 = wt*n.x*j2;
                a11 = wt*n.y*n.y; a12 = wt*n.y*j2;  a22 = wt*j2*j2;
                g0  = wt*n.x*res; g1  = wt*n.y*res; g2  = wt*j2*res;
            }
        }

        // warp tree-reduce 9 values (active warps only)
        if (wid < NACTW) {
            #pragma unroll
            for (int off = 16; off; off >>= 1) {
                a00 += __shfl_xor_sync(0xffffffffu, a00, off);
                a01 += __shfl_xor_sync(0xffffffffu, a01, off);
                a02 += __shfl_xor_sync(0xffffffffu, a02, off);
                a11 += __shfl_xor_sync(0xffffffffu, a11, off);
                a12 += __shfl_xor_sync(0xffffffffu, a12, off);
                a22 += __shfl_xor_sync(0xffffffffu, a22, off);
                g0  += __shfl_xor_sync(0xffffffffu, g0 , off);
                g1  += __shfl_xor_sync(0xffffffffu, g1 , off);
                g2  += __shfl_xor_sync(0xffffffffu, g2 , off);
            }
            if (lane == 0) {
                S.red[wid][0]=a00; S.red[wid][1]=a01; S.red[wid][2]=a02;
                S.red[wid][3]=a11; S.red[wid][4]=a12; S.red[wid][5]=a22;
                S.red[wid][6]=g0;  S.red[wid][7]=g1;  S.red[wid][8]=g2;
            }
        }
        __syncthreads();

        // warp 0: reduce warp partials; lanes 0-8 broadcast to all ranks
        if (wid == 0) {
            float r9[9];
            #pragma unroll
            for (int k = 0; k < 9; ++k) r9[k] = (lane < NACTW) ? S.red[lane][k] : 0.f;
            #pragma unroll
            for (int off = 8; off; off >>= 1) {
                #pragma unroll
                for (int k = 0; k < 9; ++k)
                    r9[k] += __shfl_xor_sync(0xffffffffu, r9[k], off);
            }
            if (lane < 9) {
                float val = (lane==0)?r9[0]:(lane==1)?r9[1]:(lane==2)?r9[2]:
                            (lane==3)?r9[3]:(lane==4)?r9[4]:(lane==5)?r9[5]:
                            (lane==6)?r9[6]:(lane==7)?r9[7]:r9[8];
                uint32_t slot = partialBase + (uint32_t)((parity*CLU + crank) * 48 + lane * 4);
                #pragma unroll
                for (int t = 0; t < CLU; ++t)
                    st_cluster_f32(mapa_rank(slot, (uint32_t)t), val);
            }
        }

        cluster_sync();  // release prior ::cluster stores; acquire for reads

        // every THREAD redundantly sums + solves (identical fp32 everywhere)
        float stepmax;
        {
            const float4* P = reinterpret_cast<const float4*>(&S.partial[parity][0][0]);
            float4 p0a = P[0], p0b = P[1], p0c = P[2];
            float4 p1a = P[3], p1b = P[4], p1c = P[5];
            float4 p2a = P[6], p2b = P[7], p2c = P[8];
            float4 p3a = P[9], p3b = P[10], p3c = P[11];
            float A00 = (p0a.x + p1a.x + p2a.x + p3a.x) + 1e-8f;
            float A01 = (p0a.y + p1a.y + p2a.y + p3a.y);
            float A02 = (p0a.z + p1a.z + p2a.z + p3a.z);
            float A11 = (p0a.w + p1a.w + p2a.w + p3a.w) + 1e-8f;
            float A12 = (p0b.x + p1b.x + p2b.x + p3b.x);
            float A22 = (p0b.y + p1b.y + p2b.y + p3b.y) + 1e-8f;
            float G0  = (p0b.z + p1b.z + p2b.z + p3b.z);
            float G1  = (p0b.w + p1b.w + p2b.w + p3b.w);
            float G2  = (p0c.x + p1c.x + p2c.x + p3c.x);
            float il00 = __frsqrt_rn(fmaxf(A00, 1e-30f));
            float l10 = A01*il00, l20 = A02*il00;
            float il11 = __frsqrt_rn(fmaxf(A11 - l10*l10, 1e-30f));
            float l21 = (A12 - l20*l10)*il11;
            float il22 = __frsqrt_rn(fmaxf(A22 - l20*l20 - l21*l21, 1e-30f));
            float y0 = -G0*il00;
            float y1 = (-G1 - l10*y0)*il11;
            float y2 = (-G2 - l20*y0 - l21*y1)*il22;
            float x2 = y2*il22;
            float x1 = (y1 - l21*x2)*il11;
            float x0 = (y0 - l10*x1 - l20*x2)*il00;
            theta += x2;
            tx += x0;
            ty += x1;
            stepmax = fmaxf(fmaxf(fabsf(x0), fabsf(x1)), fabsf(x2));
        }
        // uniform early exit: identical fp32 in every thread of every CTA
        if (stepmax < EPS_DX) break;
    }

    if (tid == 0 && crank == 0) {
        float c = cosf(theta), s = sinf(theta);
        float* T = out + b*16;
        T[0]=c;   T[1]=-s;  T[2]=0.f; T[3]=tx;
        T[4]=s;   T[5]=c;   T[6]=0.f; T[7]=ty;
        T[8]=0.f; T[9]=0.f; T[10]=1.f;T[11]=0.f;
        T[12]=0.f;T[13]=0.f;T[14]=0.f;T[15]=1.f;
    }
    // last DSMEM writes precede the final in-loop cluster.sync -> safe to exit
}

// ---------------------------------------------------------------------------
extern "C" void kernel_launch(void* const* d_in, const int* in_sizes, int n_in,
                              void* d_out, int out_size) {
    (void)in_sizes; (void)n_in; (void)out_size;
    const float* fft    = (const float*)d_in[0];
    const float* az     = (const float*)d_in[1];
    // d_in[2] = az_timestamps (unused)
    const float* map_pc = (const float*)d_in[3];
    const float* T_init = (const float*)d_in[4];
    const float* params = (const float*)d_in[5];
    float* out = (float*)d_out;

    extract_kernel<<<(B_*A_*32 + 127)/128, 128>>>(fft, az, params);

    cudaFuncSetAttribute(icp_kernel,
                         cudaFuncAttributeMaxDynamicSharedMemorySize,
                         (int)sizeof(IcpSmem));
    icp_kernel<<<B_*CLU, NTH, sizeof(IcpSmem)>>>(map_pc, T_init, out);
}